// round 2
// baseline (speedup 1.0000x reference)
#include <cuda_runtime.h>
#include <math.h>

// Problem dims (fixed by reference): B = HID = 2048, S = SEQ = 256, fp32.
constexpr int MDIM = 2048;   // rows of all matrices / hidden size
constexpr int KDIM = 2048;   // contraction dim
constexpr int NDIM = 256;    // sequence length (columns)

// GEMM tiling
constexpr int BM = 64, BN = 64, BK = 16;
constexpr int TM = 4,  TN = 4;           // per-thread tile
// threads per block = (BM/TM) * (BN/TN) = 16*16 = 256

// Scratch (no cudaMalloc allowed) — 4 x 2 MB fp32 buffers.
__device__ float g_c [MDIM * NDIM];
__device__ float g_hA[MDIM * NDIM];
__device__ float g_hB[MDIM * NDIM];
__device__ float g_p [MDIM * NDIM];

__global__ void zero_kernel(float* __restrict__ buf, int n) {
    int i = blockIdx.x * blockDim.x + threadIdx.x;
    if (i < n) buf[i] = 0.0f;
}

// out[M,N] = op( A[M,K] @ B[K,N] + add + bias ), op = tanh if applyTanh.
// add is [M,N] or null; bias is [N] (broadcast over rows) or null.
__global__ __launch_bounds__(256) void gemm_fused(
    const float* __restrict__ A,
    const float* __restrict__ B,
    float*       __restrict__ out,
    const float* __restrict__ add,
    const float* __restrict__ bias,
    int applyTanh)
{
    __shared__ __align__(16) float As[BK][BM];   // k-major: broadcast-friendly
    __shared__ __align__(16) float Bs[BK][BN];

    const int tid = threadIdx.x;
    const int tx  = tid & 15;          // N direction (0..15)
    const int ty  = tid >> 4;          // M direction (0..15)
    const int m0  = blockIdx.y * BM;
    const int n0  = blockIdx.x * BN;

    // A tile load mapping: one float4 per thread, 64 rows x 16 k
    const int aRow = tid >> 2;                 // 0..63
    const int aK4  = (tid & 3) << 2;           // 0,4,8,12
    // B tile load mapping: one float4 per thread, 16 k x 64 cols (coalesced)
    const int bRow  = tid >> 4;                // 0..15
    const int bCol4 = (tid & 15) << 2;         // 0..60

    const float* Aptr = A + (size_t)(m0 + aRow) * KDIM + aK4;
    const float* Bptr = B + (size_t)bRow * NDIM + n0 + bCol4;

    float4 aReg = *(const float4*)Aptr;
    float4 bReg = *(const float4*)Bptr;

    float acc[TM][TN] = {};

    const int nTiles = KDIM / BK;
    for (int t = 0; t < nTiles; ++t) {
        // commit prefetched regs to smem (As transposed to k-major)
        As[aK4 + 0][aRow] = aReg.x;
        As[aK4 + 1][aRow] = aReg.y;
        As[aK4 + 2][aRow] = aReg.z;
        As[aK4 + 3][aRow] = aReg.w;
        *(float4*)&Bs[bRow][bCol4] = bReg;
        __syncthreads();

        // prefetch next tile while computing this one
        if (t + 1 < nTiles) {
            aReg = *(const float4*)(Aptr + (t + 1) * BK);
            bReg = *(const float4*)(Bptr + (size_t)(t + 1) * BK * NDIM);
        }

        #pragma unroll
        for (int k = 0; k < BK; ++k) {
            float4 a4 = *(const float4*)&As[k][ty * TM];
            float4 b4 = *(const float4*)&Bs[k][tx * TN];
            float av[TM] = {a4.x, a4.y, a4.z, a4.w};
            float bv[TN] = {b4.x, b4.y, b4.z, b4.w};
            #pragma unroll
            for (int i = 0; i < TM; ++i)
                #pragma unroll
                for (int j = 0; j < TN; ++j)
                    acc[i][j] = fmaf(av[i], bv[j], acc[i][j]);
        }
        __syncthreads();
    }

    // epilogue: add + bias + tanh, vectorized stores
    const int n = n0 + tx * TN;
    float b0 = 0.f, b1 = 0.f, b2 = 0.f, b3 = 0.f;
    if (bias) { b0 = bias[n]; b1 = bias[n + 1]; b2 = bias[n + 2]; b3 = bias[n + 3]; }

    #pragma unroll
    for (int i = 0; i < TM; ++i) {
        const int m = m0 + ty * TM + i;
        float4 r = make_float4(acc[i][0] + b0, acc[i][1] + b1,
                               acc[i][2] + b2, acc[i][3] + b3);
        if (add) {
            float4 c4 = *(const float4*)(add + (size_t)m * NDIM + n);
            r.x += c4.x; r.y += c4.y; r.z += c4.z; r.w += c4.w;
        }
        if (applyTanh) {
            r.x = tanhf(r.x); r.y = tanhf(r.y);
            r.z = tanhf(r.z); r.w = tanhf(r.w);
        }
        *(float4*)(out + (size_t)m * NDIM + n) = r;
    }
}

// Row softmax over NDIM=256 columns. One warp per row, 8 rows per block.
__global__ __launch_bounds__(256) void softmax_kernel(
    const float* __restrict__ p, float* __restrict__ out)
{
    const int row  = blockIdx.x * 8 + (threadIdx.x >> 5);
    const int lane = threadIdx.x & 31;
    const float* pr = p + (size_t)row * NDIM;

    float v[8];
    float mx = -INFINITY;
    #pragma unroll
    for (int i = 0; i < 8; ++i) {
        v[i] = pr[lane + 32 * i];
        mx = fmaxf(mx, v[i]);
    }
    #pragma unroll
    for (int o = 16; o > 0; o >>= 1)
        mx = fmaxf(mx, __shfl_xor_sync(0xffffffffu, mx, o));

    float s = 0.f;
    #pragma unroll
    for (int i = 0; i < 8; ++i) { v[i] = expf(v[i] - mx); s += v[i]; }
    #pragma unroll
    for (int o = 16; o > 0; o >>= 1)
        s += __shfl_xor_sync(0xffffffffu, s, o);

    const float inv = 1.0f / s;
    float* orow = out + (size_t)row * NDIM;
    #pragma unroll
    for (int i = 0; i < 8; ++i) orow[lane + 32 * i] = v[i] * inv;
}

extern "C" void kernel_launch(void* const* d_in, const int* in_sizes, int n_in,
                              void* d_out, int out_size)
{
    const float* x   = (const float*)d_in[0];
    const float* Whx = (const float*)d_in[1];
    const float* Whh = (const float*)d_in[2];
    const float* Wph = (const float*)d_in[3];
    const float* bh  = (const float*)d_in[4];
    const float* bp  = (const float*)d_in[5];

    float *c, *hA, *hB, *p;
    cudaGetSymbolAddress((void**)&c,  g_c);
    cudaGetSymbolAddress((void**)&hA, g_hA);
    cudaGetSymbolAddress((void**)&hB, g_hB);
    cudaGetSymbolAddress((void**)&p,  g_p);

    const dim3 grid(NDIM / BN, MDIM / BM);   // (4, 32) = 128 blocks
    const int elems = MDIM * NDIM;

    // h0 = 0 (must re-zero every call: buffers are overwritten each run)
    zero_kernel<<<(elems + 255) / 256, 256>>>(hA, elems);

    // c = Whx @ x
    gemm_fused<<<grid, 256>>>(Whx, x, c, nullptr, nullptr, 0);

    // 256 recurrence steps, ping-pong hA/hB (even count -> final h in hA)
    float* hp = hA;
    float* hn = hB;
    for (int t = 0; t < NDIM; ++t) {
        gemm_fused<<<grid, 256>>>(Whh, hp, hn, c, bh, 1);
        float* tmp = hp; hp = hn; hn = tmp;
    }

    // p = Wph @ h + bp, then softmax rows -> d_out
    gemm_fused<<<grid, 256>>>(Wph, hp, p, nullptr, bp, 0);
    softmax_kernel<<<MDIM / 8, 256>>>(p, (float*)d_out);
}

// round 4
// speedup vs baseline: 1.7472x; 1.7472x over previous
#include <cuda_runtime.h>
#include <cuda_bf16.h>
#include <math.h>
#include <stdint.h>

// ---------------------------------------------------------------- dims
constexpr int MDIM = 2048, KDIM = 2048, NDIM = 256;

// ---------------------------------------------------------------- tiling
constexpr int BM = 64, BN = 64, BK = 32;
constexpr int NIT = KDIM / BK;          // 64 stages
constexpr int THREADS = 128;            // 4 warps, 2x2 of 32x32 warp tiles
constexpr int ROWP = 40;                // padded smem row (bf16 elems, 80B)
constexpr int ARR_EL = 64 * ROWP;       // one operand array (rows x ROWP)
constexpr int STAGE_EL = 4 * ARR_EL;    // Ahi, Alo, Bhi, Blo
constexpr int SMEM_BYTES = 3 * STAGE_EL * 2;   // 61440

// ---------------------------------------------------------------- scratch
__device__ __nv_bfloat16 g_WhxHi[MDIM * KDIM];
__device__ __nv_bfloat16 g_WhxLo[MDIM * KDIM];
__device__ __nv_bfloat16 g_WhhHi[MDIM * KDIM];
__device__ __nv_bfloat16 g_WhhLo[MDIM * KDIM];
__device__ __nv_bfloat16 g_WphHi[MDIM * KDIM];
__device__ __nv_bfloat16 g_WphLo[MDIM * KDIM];
__device__ __nv_bfloat16 g_xTHi[NDIM * KDIM];
__device__ __nv_bfloat16 g_xTLo[NDIM * KDIM];
__device__ __nv_bfloat16 g_h0Hi[NDIM * KDIM];
__device__ __nv_bfloat16 g_h0Lo[NDIM * KDIM];
__device__ __nv_bfloat16 g_h1Hi[NDIM * KDIM];
__device__ __nv_bfloat16 g_h1Lo[NDIM * KDIM];
__device__ float g_c[MDIM * NDIM];
__device__ float g_p[MDIM * NDIM];

// ---------------------------------------------------------------- helpers
__device__ __forceinline__ uint32_t smem_u32(const void* p) {
    uint32_t a;
    asm("{ .reg .u64 t; cvta.to.shared.u64 t, %1; cvt.u32.u64 %0, t; }"
        : "=r"(a) : "l"(p));
    return a;
}

__device__ __forceinline__ void mma_bf16(float* c, const uint32_t* a,
                                         const uint32_t* b) {
    asm volatile(
        "mma.sync.aligned.m16n8k16.row.col.f32.bf16.bf16.f32 "
        "{%0,%1,%2,%3}, {%4,%5,%6,%7}, {%8,%9}, {%0,%1,%2,%3};"
        : "+f"(c[0]), "+f"(c[1]), "+f"(c[2]), "+f"(c[3])
        : "r"(a[0]), "r"(a[1]), "r"(a[2]), "r"(a[3]), "r"(b[0]), "r"(b[1]));
}

__device__ __forceinline__ void cp16(uint32_t sdst, const void* gsrc) {
    asm volatile("cp.async.cg.shared.global [%0], [%1], 16;"
                 :: "r"(sdst), "l"(gsrc));
}

__device__ __forceinline__ void split_bf16(float v, __nv_bfloat16& hi,
                                           __nv_bfloat16& lo) {
    hi = __float2bfloat16(v);
    lo = __float2bfloat16(v - __bfloat162float(hi));
}

// ---------------------------------------------------------------- prep
__global__ void split_kernel(const float* __restrict__ src,
                             __nv_bfloat16* __restrict__ hi,
                             __nv_bfloat16* __restrict__ lo, int n) {
    int i = blockIdx.x * blockDim.x + threadIdx.x;
    if (i >= n) return;
    __nv_bfloat16 h, l;
    split_bf16(src[i], h, l);
    hi[i] = h; lo[i] = l;
}

// x[K][N] -> xT hi/lo [N][K]
__global__ void transpose_split_kernel(const float* __restrict__ x,
                                       __nv_bfloat16* __restrict__ hiT,
                                       __nv_bfloat16* __restrict__ loT) {
    int i = blockIdx.x * blockDim.x + threadIdx.x;
    if (i >= KDIM * NDIM) return;
    int k = i / NDIM, n = i % NDIM;
    __nv_bfloat16 h, l;
    split_bf16(x[i], h, l);
    hiT[(size_t)n * KDIM + k] = h;
    loT[(size_t)n * KDIM + k] = l;
}

__global__ void zero_bf16x2_kernel(__nv_bfloat16* __restrict__ a,
                                   __nv_bfloat16* __restrict__ b, int n4) {
    int i = blockIdx.x * blockDim.x + threadIdx.x;
    if (i < n4) {
        ((uint64_t*)a)[i] = 0ull;
        ((uint64_t*)b)[i] = 0ull;
    }
}

// ---------------------------------------------------------------- main GEMM
// D[BM,BN] = Ahi/lo[M,K] @ (Bhi/lo[N,K])^T  via bf16x3 mma.sync
// mode 0: outF = D
// mode 1: outF = D + bias
// mode 2: v = tanh(D + addc + bias); outHi/outLo = bf16 split of v,
//         written TRANSPOSED [N][K] for the next step's B operand.
__global__ void __launch_bounds__(THREADS) rnn_gemm(
    const __nv_bfloat16* __restrict__ Ahi, const __nv_bfloat16* __restrict__ Alo,
    const __nv_bfloat16* __restrict__ Bhi, const __nv_bfloat16* __restrict__ Blo,
    const float* __restrict__ addc, const float* __restrict__ bias,
    float* __restrict__ outF,
    __nv_bfloat16* __restrict__ outHi, __nv_bfloat16* __restrict__ outLo,
    int mode)
{
    extern __shared__ __align__(16) __nv_bfloat16 sm[];
    const int tid  = threadIdx.x;
    const int lane = tid & 31;
    const int wid  = tid >> 5;
    const int wm0  = (wid & 1) * 32;
    const int wn0  = (wid >> 1) * 32;
    const int m0   = blockIdx.y * BM;
    const int n0   = blockIdx.x * BN;

    float C[2][4][4] = {};

    // stage loader: 1024 x 16B chunks, 8 per thread
    auto issue_stage = [&](int it) {
        const int s  = it % 3;
        const int k0 = it * BK;
        __nv_bfloat16* st = sm + s * STAGE_EL;
        const int row0 = tid >> 2;
        const int q    = tid & 3;
        #pragma unroll
        for (int i = 0; i < 8; ++i) {
            const int arr = i >> 1;                   // 0 Ahi,1 Alo,2 Bhi,3 Blo
            const int row = row0 + 32 * (i & 1);
            const __nv_bfloat16* g;
            if (arr == 0)      g = Ahi + (size_t)(m0 + row) * KDIM + k0 + q * 8;
            else if (arr == 1) g = Alo + (size_t)(m0 + row) * KDIM + k0 + q * 8;
            else if (arr == 2) g = Bhi + (size_t)(n0 + row) * KDIM + k0 + q * 8;
            else               g = Blo + (size_t)(n0 + row) * KDIM + k0 + q * 8;
            cp16(smem_u32(st + arr * ARR_EL + row * ROWP + q * 8), g);
        }
        asm volatile("cp.async.commit_group;" ::: "memory");
    };

    issue_stage(0);
    issue_stage(1);

    for (int it = 0; it < NIT; ++it) {
        asm volatile("cp.async.wait_group 1;" ::: "memory");
        __syncthreads();
        if (it + 2 < NIT) issue_stage(it + 2);
        else asm volatile("cp.async.commit_group;" ::: "memory");

        const __nv_bfloat16* st  = sm + (it % 3) * STAGE_EL;
        const __nv_bfloat16* sAh = st;
        const __nv_bfloat16* sAl = st + ARR_EL;
        const __nv_bfloat16* sBh = st + 2 * ARR_EL;
        const __nv_bfloat16* sBl = st + 3 * ARR_EL;

        #pragma unroll
        for (int kk = 0; kk < 2; ++kk) {
            const int kb = kk * 16 + 2 * (lane & 3);

            uint32_t ah[2][4], al[2][4];
            #pragma unroll
            for (int mt = 0; mt < 2; ++mt) {
                const int r = wm0 + mt * 16 + (lane >> 2);
                const __nv_bfloat16* p0 = sAh + r * ROWP + kb;
                const __nv_bfloat16* p1 = sAh + (r + 8) * ROWP + kb;
                ah[mt][0] = *(const uint32_t*)p0;
                ah[mt][1] = *(const uint32_t*)p1;
                ah[mt][2] = *(const uint32_t*)(p0 + 8);
                ah[mt][3] = *(const uint32_t*)(p1 + 8);
                const __nv_bfloat16* q0 = sAl + r * ROWP + kb;
                const __nv_bfloat16* q1 = sAl + (r + 8) * ROWP + kb;
                al[mt][0] = *(const uint32_t*)q0;
                al[mt][1] = *(const uint32_t*)q1;
                al[mt][2] = *(const uint32_t*)(q0 + 8);
                al[mt][3] = *(const uint32_t*)(q1 + 8);
            }
            uint32_t bh[4][2], bl[4][2];
            #pragma unroll
            for (int nt = 0; nt < 4; ++nt) {
                const int n = wn0 + nt * 8 + (lane >> 2);
                const __nv_bfloat16* p = sBh + n * ROWP + kb;
                bh[nt][0] = *(const uint32_t*)p;
                bh[nt][1] = *(const uint32_t*)(p + 8);
                const __nv_bfloat16* q = sBl + n * ROWP + kb;
                bl[nt][0] = *(const uint32_t*)q;
                bl[nt][1] = *(const uint32_t*)(q + 8);
            }
            #pragma unroll
            for (int mt = 0; mt < 2; ++mt)
                #pragma unroll
                for (int nt = 0; nt < 4; ++nt) {
                    mma_bf16(C[mt][nt], ah[mt], bh[nt]);
                    mma_bf16(C[mt][nt], ah[mt], bl[nt]);
                    mma_bf16(C[mt][nt], al[mt], bh[nt]);
                }
        }
        __syncthreads();
    }

    // ------------------------------------------------------------ epilogue
    if (mode == 2) {
        __nv_bfloat16* th = sm;                 // [64][72] transposed hi
        __nv_bfloat16* tl = sm + 64 * 72;       // [64][72] transposed lo
        #pragma unroll
        for (int mt = 0; mt < 2; ++mt)
            #pragma unroll
            for (int nt = 0; nt < 4; ++nt) {
                const int lr = wm0 + mt * 16 + (lane >> 2);
                const int lc = wn0 + nt * 8 + 2 * (lane & 3);
                const int gm = m0 + lr, gn = n0 + lc;
                float2 c0 = *(const float2*)(addc + (size_t)gm * NDIM + gn);
                float2 c1 = *(const float2*)(addc + (size_t)(gm + 8) * NDIM + gn);
                float2 bv = *(const float2*)(bias + gn);
                float v00 = tanhf(C[mt][nt][0] + c0.x + bv.x);
                float v01 = tanhf(C[mt][nt][1] + c0.y + bv.y);
                float v10 = tanhf(C[mt][nt][2] + c1.x + bv.x);
                float v11 = tanhf(C[mt][nt][3] + c1.y + bv.y);
                __nv_bfloat16 h, l;
                split_bf16(v00, h, l); th[lc * 72 + lr] = h;       tl[lc * 72 + lr] = l;
                split_bf16(v01, h, l); th[(lc + 1) * 72 + lr] = h; tl[(lc + 1) * 72 + lr] = l;
                split_bf16(v10, h, l); th[lc * 72 + lr + 8] = h;   tl[lc * 72 + lr + 8] = l;
                split_bf16(v11, h, l); th[(lc + 1) * 72 + lr + 8] = h;
                                       tl[(lc + 1) * 72 + lr + 8] = l;
            }
        __syncthreads();
        const int col = tid & 63, half = tid >> 6;
        #pragma unroll
        for (int j = 0; j < 4; ++j) {
            const int r = half * 32 + j * 8;
            uint4 vh = *(const uint4*)&th[col * 72 + r];
            uint4 vl = *(const uint4*)&tl[col * 72 + r];
            *(uint4*)&outHi[(size_t)(n0 + col) * KDIM + m0 + r] = vh;
            *(uint4*)&outLo[(size_t)(n0 + col) * KDIM + m0 + r] = vl;
        }
    } else {
        #pragma unroll
        for (int mt = 0; mt < 2; ++mt)
            #pragma unroll
            for (int nt = 0; nt < 4; ++nt) {
                const int lr = wm0 + mt * 16 + (lane >> 2);
                const int lc = wn0 + nt * 8 + 2 * (lane & 3);
                const int gm = m0 + lr, gn = n0 + lc;
                float bx = 0.f, by = 0.f;
                if (mode == 1) {
                    float2 bv = *(const float2*)(bias + gn);
                    bx = bv.x; by = bv.y;
                }
                float2 o0 = make_float2(C[mt][nt][0] + bx, C[mt][nt][1] + by);
                float2 o1 = make_float2(C[mt][nt][2] + bx, C[mt][nt][3] + by);
                *(float2*)(outF + (size_t)gm * NDIM + gn) = o0;
                *(float2*)(outF + (size_t)(gm + 8) * NDIM + gn) = o1;
            }
    }
}

// ---------------------------------------------------------------- softmax
__global__ __launch_bounds__(256) void softmax_kernel(
    const float* __restrict__ p, float* __restrict__ out)
{
    const int row  = blockIdx.x * 8 + (threadIdx.x >> 5);
    const int lane = threadIdx.x & 31;
    const float* pr = p + (size_t)row * NDIM;
    float v[8];
    float mx = -INFINITY;
    #pragma unroll
    for (int i = 0; i < 8; ++i) { v[i] = pr[lane + 32 * i]; mx = fmaxf(mx, v[i]); }
    #pragma unroll
    for (int o = 16; o > 0; o >>= 1) mx = fmaxf(mx, __shfl_xor_sync(~0u, mx, o));
    float s = 0.f;
    #pragma unroll
    for (int i = 0; i < 8; ++i) { v[i] = expf(v[i] - mx); s += v[i]; }
    #pragma unroll
    for (int o = 16; o > 0; o >>= 1) s += __shfl_xor_sync(~0u, s, o);
    const float inv = 1.0f / s;
    float* orow = out + (size_t)row * NDIM;
    #pragma unroll
    for (int i = 0; i < 8; ++i) orow[lane + 32 * i] = v[i] * inv;
}

// ---------------------------------------------------------------- launch
extern "C" void kernel_launch(void* const* d_in, const int* in_sizes, int n_in,
                              void* d_out, int out_size)
{
    const float* x   = (const float*)d_in[0];
    const float* Whx = (const float*)d_in[1];
    const float* Whh = (const float*)d_in[2];
    const float* Wph = (const float*)d_in[3];
    const float* bh  = (const float*)d_in[4];
    const float* bp  = (const float*)d_in[5];

    __nv_bfloat16 *whxH, *whxL, *whhH, *whhL, *wphH, *wphL;
    __nv_bfloat16 *xtH, *xtL, *h0H, *h0L, *h1H, *h1L;
    float *c, *p;
    cudaGetSymbolAddress((void**)&whxH, g_WhxHi);
    cudaGetSymbolAddress((void**)&whxL, g_WhxLo);
    cudaGetSymbolAddress((void**)&whhH, g_WhhHi);
    cudaGetSymbolAddress((void**)&whhL, g_WhhLo);
    cudaGetSymbolAddress((void**)&wphH, g_WphHi);
    cudaGetSymbolAddress((void**)&wphL, g_WphLo);
    cudaGetSymbolAddress((void**)&xtH,  g_xTHi);
    cudaGetSymbolAddress((void**)&xtL,  g_xTLo);
    cudaGetSymbolAddress((void**)&h0H,  g_h0Hi);
    cudaGetSymbolAddress((void**)&h0L,  g_h0Lo);
    cudaGetSymbolAddress((void**)&h1H,  g_h1Hi);
    cudaGetSymbolAddress((void**)&h1L,  g_h1Lo);
    cudaGetSymbolAddress((void**)&c,    g_c);
    cudaGetSymbolAddress((void**)&p,    g_p);

    cudaFuncSetAttribute(rnn_gemm, cudaFuncAttributeMaxDynamicSharedMemorySize,
                         SMEM_BYTES);

    const int WN = MDIM * KDIM;
    split_kernel<<<(WN + 255) / 256, 256>>>(Whx, whxH, whxL, WN);
    split_kernel<<<(WN + 255) / 256, 256>>>(Whh, whhH, whhL, WN);
    split_kernel<<<(WN + 255) / 256, 256>>>(Wph, wphH, wphL, WN);
    transpose_split_kernel<<<(KDIM * NDIM + 255) / 256, 256>>>(x, xtH, xtL);
    zero_bf16x2_kernel<<<(NDIM * KDIM / 4 + 255) / 256, 256>>>(h0H, h0L,
                                                               NDIM * KDIM / 4);

    const dim3 grid(NDIM / BN, MDIM / BM);   // (4, 32) = 128 CTAs

    // c = Whx @ x
    rnn_gemm<<<grid, THREADS, SMEM_BYTES>>>(whxH, whxL, xtH, xtL,
                                            nullptr, nullptr, c,
                                            nullptr, nullptr, 0);

    // 256 steps: h' = tanh(c + Whh@h + bh) -> transposed bf16 hi/lo
    __nv_bfloat16 *phH = h0H, *phL = h0L, *pnH = h1H, *pnL = h1L;
    for (int t = 0; t < NDIM; ++t) {
        rnn_gemm<<<grid, THREADS, SMEM_BYTES>>>(whhH, whhL, phH, phL,
                                                c, bh, nullptr,
                                                pnH, pnL, 2);
        __nv_bfloat16* tm;
        tm = phH; phH = pnH; pnH = tm;
        tm = phL; phL = pnL; pnL = tm;
    }

    // p = Wph @ h + bp; softmax
    rnn_gemm<<<grid, THREADS, SMEM_BYTES>>>(wphH, wphL, phH, phL,
                                            nullptr, bp, p,
                                            nullptr, nullptr, 1);
    softmax_kernel<<<MDIM / 8, 256>>>(p, (float*)d_out);
}

// round 5
// speedup vs baseline: 2.0847x; 1.1932x over previous
#include <cuda_runtime.h>
#include <cuda_bf16.h>
#include <math.h>
#include <stdint.h>

// ---------------------------------------------------------------- dims
constexpr int MDIM = 2048, KDIM = 2048, NDIM = 256;

// ---------------------------------------------------------------- tiling
constexpr int BM = 64, BN = 64, BK = 32;
constexpr int NIT = KDIM / BK;              // 64
constexpr int THREADS = 256;                // 8 warps: 2 (m) x 4 (n)
constexpr int ROWP = 40;                    // padded row, bf16 elems (80 B)
constexpr int ARR_BYTES = 64 * ROWP * 2;    // 5120 B per operand array
constexpr int STAGE_BYTES = 4 * ARR_BYTES;  // Ahi, Alo, Bhi, Blo = 20480 B
constexpr int SMEM_BYTES = 3 * STAGE_BYTES; // 61440 B

// ---------------------------------------------------------------- scratch
__device__ __nv_bfloat16 g_WhxHi[MDIM * KDIM];
__device__ __nv_bfloat16 g_WhxLo[MDIM * KDIM];
__device__ __nv_bfloat16 g_WhhHi[MDIM * KDIM];
__device__ __nv_bfloat16 g_WhhLo[MDIM * KDIM];
__device__ __nv_bfloat16 g_WphHi[MDIM * KDIM];
__device__ __nv_bfloat16 g_WphLo[MDIM * KDIM];
__device__ __nv_bfloat16 g_xTHi[NDIM * KDIM];
__device__ __nv_bfloat16 g_xTLo[NDIM * KDIM];
__device__ __nv_bfloat16 g_h0Hi[NDIM * KDIM];
__device__ __nv_bfloat16 g_h0Lo[NDIM * KDIM];
__device__ __nv_bfloat16 g_h1Hi[NDIM * KDIM];
__device__ __nv_bfloat16 g_h1Lo[NDIM * KDIM];
__device__ float g_c[MDIM * NDIM];
__device__ float g_p[MDIM * NDIM];

// ---------------------------------------------------------------- helpers
__device__ __forceinline__ uint32_t smem_u32(const void* p) {
    uint32_t a;
    asm("{ .reg .u64 t; cvta.to.shared.u64 t, %1; cvt.u32.u64 %0, t; }"
        : "=r"(a) : "l"(p));
    return a;
}

__device__ __forceinline__ void mma_bf16(float* c, const uint32_t* a,
                                         const uint32_t* b) {
    asm volatile(
        "mma.sync.aligned.m16n8k16.row.col.f32.bf16.bf16.f32 "
        "{%0,%1,%2,%3}, {%4,%5,%6,%7}, {%8,%9}, {%0,%1,%2,%3};"
        : "+f"(c[0]), "+f"(c[1]), "+f"(c[2]), "+f"(c[3])
        : "r"(a[0]), "r"(a[1]), "r"(a[2]), "r"(a[3]), "r"(b[0]), "r"(b[1]));
}

__device__ __forceinline__ void ldsm_x4(uint32_t* r, uint32_t addr) {
    asm volatile("ldmatrix.sync.aligned.m8n8.x4.shared.b16 {%0,%1,%2,%3}, [%4];"
                 : "=r"(r[0]), "=r"(r[1]), "=r"(r[2]), "=r"(r[3]) : "r"(addr));
}

__device__ __forceinline__ void cp16(uint32_t sdst, const void* gsrc) {
    asm volatile("cp.async.cg.shared.global [%0], [%1], 16;"
                 :: "r"(sdst), "l"(gsrc));
}

__device__ __forceinline__ void split_bf16(float v, __nv_bfloat16& hi,
                                           __nv_bfloat16& lo) {
    hi = __float2bfloat16(v);
    lo = __float2bfloat16(v - __bfloat162float(hi));
}

// ---------------------------------------------------------------- prep
__global__ void split_kernel(const float* __restrict__ src,
                             __nv_bfloat16* __restrict__ hi,
                             __nv_bfloat16* __restrict__ lo, int n) {
    int i = blockIdx.x * blockDim.x + threadIdx.x;
    if (i >= n) return;
    __nv_bfloat16 h, l;
    split_bf16(src[i], h, l);
    hi[i] = h; lo[i] = l;
}

// x[K][N] -> xT hi/lo [N][K]
__global__ void transpose_split_kernel(const float* __restrict__ x,
                                       __nv_bfloat16* __restrict__ hiT,
                                       __nv_bfloat16* __restrict__ loT) {
    int i = blockIdx.x * blockDim.x + threadIdx.x;
    if (i >= KDIM * NDIM) return;
    int k = i / NDIM, n = i % NDIM;
    __nv_bfloat16 h, l;
    split_bf16(x[i], h, l);
    hiT[(size_t)n * KDIM + k] = h;
    loT[(size_t)n * KDIM + k] = l;
}

// step 1 (h0 = 0): h1 = tanh(c + bh), split + transpose to [N][K]
__global__ void first_step_kernel(const float* __restrict__ c,
                                  const float* __restrict__ bh,
                                  __nv_bfloat16* __restrict__ outHi,
                                  __nv_bfloat16* __restrict__ outLo) {
    int i = blockIdx.x * blockDim.x + threadIdx.x;
    if (i >= MDIM * NDIM) return;
    int m = i / NDIM, n = i % NDIM;
    float v = tanhf(c[i] + bh[n]);
    __nv_bfloat16 h, l;
    split_bf16(v, h, l);
    outHi[(size_t)n * KDIM + m] = h;
    outLo[(size_t)n * KDIM + m] = l;
}

// ---------------------------------------------------------------- main GEMM
// D[BM,BN] = Ahi/lo[M,K] @ (Bhi/lo[N,K])^T  via bf16x3 mma.sync
// mode 0: outF = D
// mode 1: outF = D + bias
// mode 2: v = tanh(D + addc + bias); bf16-split of v stored TRANSPOSED [N][K]
__global__ void __launch_bounds__(THREADS) rnn_gemm(
    const __nv_bfloat16* __restrict__ Ahi, const __nv_bfloat16* __restrict__ Alo,
    const __nv_bfloat16* __restrict__ Bhi, const __nv_bfloat16* __restrict__ Blo,
    const float* __restrict__ addc, const float* __restrict__ bias,
    float* __restrict__ outF,
    __nv_bfloat16* __restrict__ outHi, __nv_bfloat16* __restrict__ outLo,
    int mode)
{
    extern __shared__ __align__(16) char sm[];
    const uint32_t sbase = smem_u32(sm);
    const int tid  = threadIdx.x;
    const int lane = tid & 31;
    const int wid  = tid >> 5;
    const int wm0  = (wid & 1) * 32;     // warp m-offset (2 warps in m)
    const int wn0  = (wid >> 1) * 16;    // warp n-offset (4 warps in n)
    const int m0   = blockIdx.y * BM;
    const int n0   = blockIdx.x * BN;

    float C[2][2][4] = {};

    // ldmatrix lane offsets (bytes)
    const uint32_t aoff = (uint32_t)((lane & 15) * 80 + (lane >> 4) * 16);
    const uint32_t boff = (uint32_t)((lane & 7) * 80 + ((lane >> 4) & 1) * 640 +
                                     ((lane >> 3) & 1) * 16);

    // stage loader: 1024 x 16B chunks, 4 per thread
    auto issue_stage = [&](int it) {
        const int s  = it % 3;
        const int k0 = it * BK;
        const uint32_t st = sbase + s * STAGE_BYTES;
        #pragma unroll
        for (int i = 0; i < 4; ++i) {
            const int cid = tid + 256 * i;
            const int arr = cid >> 8;          // 0 Ahi, 1 Alo, 2 Bhi, 3 Blo
            const int wi  = cid & 255;
            const int row = wi >> 2;
            const int q   = wi & 3;
            const __nv_bfloat16* g;
            if (arr == 0)      g = Ahi + (size_t)(m0 + row) * KDIM + k0 + q * 8;
            else if (arr == 1) g = Alo + (size_t)(m0 + row) * KDIM + k0 + q * 8;
            else if (arr == 2) g = Bhi + (size_t)(n0 + row) * KDIM + k0 + q * 8;
            else               g = Blo + (size_t)(n0 + row) * KDIM + k0 + q * 8;
            cp16(st + arr * ARR_BYTES + row * 80 + q * 16, g);
        }
        asm volatile("cp.async.commit_group;" ::: "memory");
    };

    issue_stage(0);
    issue_stage(1);

    for (int it = 0; it < NIT; ++it) {
        asm volatile("cp.async.wait_group 1;" ::: "memory");
        __syncthreads();
        if (it + 2 < NIT) issue_stage(it + 2);
        else asm volatile("cp.async.commit_group;" ::: "memory");

        const uint32_t st  = sbase + (it % 3) * STAGE_BYTES;
        const uint32_t sAh = st;
        const uint32_t sAl = st + ARR_BYTES;
        const uint32_t sBh = st + 2 * ARR_BYTES;
        const uint32_t sBl = st + 3 * ARR_BYTES;

        #pragma unroll
        for (int kk = 0; kk < 2; ++kk) {
            const uint32_t kb = kk * 32;     // 16 bf16 = 32 B
            uint32_t ah[2][4], al[2][4], bh[4], bl[4];
            ldsm_x4(ah[0], sAh + (uint32_t)(wm0 * 80) + kb + aoff);
            ldsm_x4(ah[1], sAh + (uint32_t)((wm0 + 16) * 80) + kb + aoff);
            ldsm_x4(al[0], sAl + (uint32_t)(wm0 * 80) + kb + aoff);
            ldsm_x4(al[1], sAl + (uint32_t)((wm0 + 16) * 80) + kb + aoff);
            ldsm_x4(bh, sBh + (uint32_t)(wn0 * 80) + kb + boff);
            ldsm_x4(bl, sBl + (uint32_t)(wn0 * 80) + kb + boff);
            #pragma unroll
            for (int mt = 0; mt < 2; ++mt)
                #pragma unroll
                for (int nt = 0; nt < 2; ++nt) {
                    mma_bf16(C[mt][nt], ah[mt], &bh[nt * 2]);
                    mma_bf16(C[mt][nt], ah[mt], &bl[nt * 2]);
                    mma_bf16(C[mt][nt], al[mt], &bh[nt * 2]);
                }
        }
    }

    // ------------------------------------------------------------ epilogue
    if (mode == 2) {
        __syncthreads();    // done reading tile stages; reuse smem
        __nv_bfloat16* th = (__nv_bfloat16*)sm;            // [64][72] hi (n,m)
        __nv_bfloat16* tl = (__nv_bfloat16*)sm + 64 * 72;  // [64][72] lo
        #pragma unroll
        for (int mt = 0; mt < 2; ++mt)
            #pragma unroll
            for (int nt = 0; nt < 2; ++nt) {
                const int lr = wm0 + mt * 16 + (lane >> 2);
                const int lc = wn0 + nt * 8 + 2 * (lane & 3);
                const int gm = m0 + lr, gn = n0 + lc;
                float2 c0 = *(const float2*)(addc + (size_t)gm * NDIM + gn);
                float2 c1 = *(const float2*)(addc + (size_t)(gm + 8) * NDIM + gn);
                float2 bv = *(const float2*)(bias + gn);
                float v00 = tanhf(C[mt][nt][0] + c0.x + bv.x);
                float v01 = tanhf(C[mt][nt][1] + c0.y + bv.y);
                float v10 = tanhf(C[mt][nt][2] + c1.x + bv.x);
                float v11 = tanhf(C[mt][nt][3] + c1.y + bv.y);
                __nv_bfloat16 h, l;
                split_bf16(v00, h, l); th[lc * 72 + lr] = h;       tl[lc * 72 + lr] = l;
                split_bf16(v01, h, l); th[(lc + 1) * 72 + lr] = h; tl[(lc + 1) * 72 + lr] = l;
                split_bf16(v10, h, l); th[lc * 72 + lr + 8] = h;   tl[lc * 72 + lr + 8] = l;
                split_bf16(v11, h, l); th[(lc + 1) * 72 + lr + 8] = h;
                                       tl[(lc + 1) * 72 + lr + 8] = l;
            }
        __syncthreads();
        const int row = tid >> 2;         // n index 0..63
        const int q   = tid & 3;
        #pragma unroll
        for (int j = 0; j < 2; ++j) {
            const int ch = q + j * 4;     // 8-elem chunk 0..7
            uint4 vh = *(const uint4*)&th[row * 72 + ch * 8];
            uint4 vl = *(const uint4*)&tl[row * 72 + ch * 8];
            *(uint4*)&outHi[(size_t)(n0 + row) * KDIM + m0 + ch * 8] = vh;
            *(uint4*)&outLo[(size_t)(n0 + row) * KDIM + m0 + ch * 8] = vl;
        }
    } else {
        #pragma unroll
        for (int mt = 0; mt < 2; ++mt)
            #pragma unroll
            for (int nt = 0; nt < 2; ++nt) {
                const int lr = wm0 + mt * 16 + (lane >> 2);
                const int lc = wn0 + nt * 8 + 2 * (lane & 3);
                const int gm = m0 + lr, gn = n0 + lc;
                float bx = 0.f, by = 0.f;
                if (mode == 1) {
                    float2 bv = *(const float2*)(bias + gn);
                    bx = bv.x; by = bv.y;
                }
                float2 o0 = make_float2(C[mt][nt][0] + bx, C[mt][nt][1] + by);
                float2 o1 = make_float2(C[mt][nt][2] + bx, C[mt][nt][3] + by);
                *(float2*)(outF + (size_t)gm * NDIM + gn) = o0;
                *(float2*)(outF + (size_t)(gm + 8) * NDIM + gn) = o1;
            }
    }
}

// ---------------------------------------------------------------- softmax
__global__ __launch_bounds__(256) void softmax_kernel(
    const float* __restrict__ p, float* __restrict__ out)
{
    const int row  = blockIdx.x * 8 + (threadIdx.x >> 5);
    const int lane = threadIdx.x & 31;
    const float* pr = p + (size_t)row * NDIM;
    float v[8];
    float mx = -INFINITY;
    #pragma unroll
    for (int i = 0; i < 8; ++i) { v[i] = pr[lane + 32 * i]; mx = fmaxf(mx, v[i]); }
    #pragma unroll
    for (int o = 16; o > 0; o >>= 1) mx = fmaxf(mx, __shfl_xor_sync(~0u, mx, o));
    float s = 0.f;
    #pragma unroll
    for (int i = 0; i < 8; ++i) { v[i] = expf(v[i] - mx); s += v[i]; }
    #pragma unroll
    for (int o = 16; o > 0; o >>= 1) s += __shfl_xor_sync(~0u, s, o);
    const float inv = 1.0f / s;
    float* orow = out + (size_t)row * NDIM;
    #pragma unroll
    for (int i = 0; i < 8; ++i) orow[lane + 32 * i] = v[i] * inv;
}

// ---------------------------------------------------------------- launch
extern "C" void kernel_launch(void* const* d_in, const int* in_sizes, int n_in,
                              void* d_out, int out_size)
{
    const float* x   = (const float*)d_in[0];
    const float* Whx = (const float*)d_in[1];
    const float* Whh = (const float*)d_in[2];
    const float* Wph = (const float*)d_in[3];
    const float* bh  = (const float*)d_in[4];
    const float* bp  = (const float*)d_in[5];

    __nv_bfloat16 *whxH, *whxL, *whhH, *whhL, *wphH, *wphL;
    __nv_bfloat16 *xtH, *xtL, *h0H, *h0L, *h1H, *h1L;
    float *c, *p;
    cudaGetSymbolAddress((void**)&whxH, g_WhxHi);
    cudaGetSymbolAddress((void**)&whxL, g_WhxLo);
    cudaGetSymbolAddress((void**)&whhH, g_WhhHi);
    cudaGetSymbolAddress((void**)&whhL, g_WhhLo);
    cudaGetSymbolAddress((void**)&wphH, g_WphHi);
    cudaGetSymbolAddress((void**)&wphL, g_WphLo);
    cudaGetSymbolAddress((void**)&xtH,  g_xTHi);
    cudaGetSymbolAddress((void**)&xtL,  g_xTLo);
    cudaGetSymbolAddress((void**)&h0H,  g_h0Hi);
    cudaGetSymbolAddress((void**)&h0L,  g_h0Lo);
    cudaGetSymbolAddress((void**)&h1H,  g_h1Hi);
    cudaGetSymbolAddress((void**)&h1L,  g_h1Lo);
    cudaGetSymbolAddress((void**)&c,    g_c);
    cudaGetSymbolAddress((void**)&p,    g_p);

    cudaFuncSetAttribute(rnn_gemm, cudaFuncAttributeMaxDynamicSharedMemorySize,
                         SMEM_BYTES);

    const int WN = MDIM * KDIM;
    split_kernel<<<(WN + 255) / 256, 256>>>(Whx, whxH, whxL, WN);
    split_kernel<<<(WN + 255) / 256, 256>>>(Whh, whhH, whhL, WN);
    split_kernel<<<(WN + 255) / 256, 256>>>(Wph, wphH, wphL, WN);
    transpose_split_kernel<<<(KDIM * NDIM + 255) / 256, 256>>>(x, xtH, xtL);

    const dim3 grid(NDIM / BN, MDIM / BM);   // (4, 32) = 128 CTAs

    // c = Whx @ x
    rnn_gemm<<<grid, THREADS, SMEM_BYTES>>>(whxH, whxL, xtH, xtL,
                                            nullptr, nullptr, c,
                                            nullptr, nullptr, 0);

    // step 1: h1 = tanh(c + bh) (h0 = 0), transposed bf16 split
    first_step_kernel<<<(MDIM * NDIM + 255) / 256, 256>>>(c, bh, h0H, h0L);

    // steps 2..256
    __nv_bfloat16 *phH = h0H, *phL = h0L, *pnH = h1H, *pnL = h1L;
    for (int t = 1; t < NDIM; ++t) {
        rnn_gemm<<<grid, THREADS, SMEM_BYTES>>>(whhH, whhL, phH, phL,
                                                c, bh, nullptr,
                                                pnH, pnL, 2);
        __nv_bfloat16* tm;
        tm = phH; phH = pnH; pnH = tm;
        tm = phL; phL = pnL; pnL = tm;
    }

    // p = Wph @ h + bp; softmax
    rnn_gemm<<<grid, THREADS, SMEM_BYTES>>>(wphH, wphL, phH, phL,
                                            nullptr, bp, p,
                                            nullptr, nullptr, 1);
    softmax_kernel<<<MDIM / 8, 256>>>(p, (float*)d_out);
}

// round 6
// speedup vs baseline: 3.7035x; 1.7765x over previous
#include <cuda_runtime.h>
#include <math.h>
#include <stdint.h>

// ---------------------------------------------------------------- dims
constexpr int MDIM = 2048, KDIM = 2048, NDIM = 256;

// ---------------------------------------------------------------- tiling
constexpr int BM = 64, BN = 64, BK = 64;     // BK = 64 int8 per stage row
constexpr int NIT = KDIM / BK;               // 32
constexpr int THREADS = 256;                 // 8 warps: 2 (m) x 4 (n)
constexpr int ROWB = 80;                     // padded row bytes (64 data + 16)
constexpr int ARR_BYTES = 64 * ROWB;         // 5120 B per operand array
constexpr int STAGE_BYTES = 4 * ARR_BYTES;   // a1, a2, b1, b2 = 20480 B
constexpr int SMEM_BYTES = 3 * STAGE_BYTES;  // 61440 B

// ---------------------------------------------------------------- scratch
__device__ int8_t g_WhxA1[MDIM * KDIM];
__device__ int8_t g_WhxA2[MDIM * KDIM];
__device__ int8_t g_WhhA1[MDIM * KDIM];
__device__ int8_t g_WhhA2[MDIM * KDIM];
__device__ int8_t g_WphA1[MDIM * KDIM];
__device__ int8_t g_WphA2[MDIM * KDIM];
__device__ int8_t g_xB1[NDIM * KDIM];
__device__ int8_t g_xB2[NDIM * KDIM];
__device__ int8_t g_h0B1[NDIM * KDIM];
__device__ int8_t g_h0B2[NDIM * KDIM];
__device__ int8_t g_h1B1[NDIM * KDIM];
__device__ int8_t g_h1B2[NDIM * KDIM];
__device__ float  g_c[MDIM * NDIM];
__device__ float  g_p[MDIM * NDIM];
__device__ int    g_maxbits[4];              // maxabs of Whx, Whh, Wph, x

// ---------------------------------------------------------------- helpers
__device__ __forceinline__ uint32_t smem_u32(const void* p) {
    uint32_t a;
    asm("{ .reg .u64 t; cvta.to.shared.u64 t, %1; cvt.u32.u64 %0, t; }"
        : "=r"(a) : "l"(p));
    return a;
}

__device__ __forceinline__ void mma_s8(int* c, const uint32_t* a,
                                       const uint32_t* b) {
    asm volatile(
        "mma.sync.aligned.m16n8k32.row.col.s32.s8.s8.s32 "
        "{%0,%1,%2,%3}, {%4,%5,%6,%7}, {%8,%9}, {%0,%1,%2,%3};"
        : "+r"(c[0]), "+r"(c[1]), "+r"(c[2]), "+r"(c[3])
        : "r"(a[0]), "r"(a[1]), "r"(a[2]), "r"(a[3]), "r"(b[0]), "r"(b[1]));
}

__device__ __forceinline__ void ldsm_x4(uint32_t* r, uint32_t addr) {
    asm volatile("ldmatrix.sync.aligned.m8n8.x4.shared.b16 {%0,%1,%2,%3}, [%4];"
                 : "=r"(r[0]), "=r"(r[1]), "=r"(r[2]), "=r"(r[3]) : "r"(addr));
}

__device__ __forceinline__ void cp16(uint32_t sdst, const void* gsrc) {
    asm volatile("cp.async.cg.shared.global [%0], [%1], 16;"
                 :: "r"(sdst), "l"(gsrc));
}

// quantize q in [-127,127] to two int8 digits: q ~= d1 + d2/256
__device__ __forceinline__ void quant2(float q, int8_t& d1, int8_t& d2) {
    float b1 = rintf(q);
    float b2 = rintf((q - b1) * 256.0f);
    b2 = fminf(fmaxf(b2, -127.0f), 127.0f);
    d1 = (int8_t)(int)b1;
    d2 = (int8_t)(int)b2;
}

// ---------------------------------------------------------------- prep
__global__ void reset_kernel() {
    if (threadIdx.x < 4) g_maxbits[threadIdx.x] = 0;
}

// maxabs per tensor; blockIdx.y selects tensor
__global__ void maxabs_kernel(const float* __restrict__ w0,
                              const float* __restrict__ w1,
                              const float* __restrict__ w2,
                              const float* __restrict__ x) {
    const int t = blockIdx.y;
    const float* src = (t == 0) ? w0 : (t == 1) ? w1 : (t == 2) ? w2 : x;
    const int len = (t == 3) ? KDIM * NDIM : MDIM * KDIM;
    float m = 0.0f;
    for (int i = blockIdx.x * 256 + threadIdx.x; i < len; i += 2048 * 256)
        m = fmaxf(m, fabsf(src[i]));
    #pragma unroll
    for (int o = 16; o > 0; o >>= 1)
        m = fmaxf(m, __shfl_xor_sync(~0u, m, o));
    if ((threadIdx.x & 31) == 0)
        atomicMax(&g_maxbits[t], __float_as_int(m));
}

// quantize tensors; blockIdx.y selects tensor; x is transposed to [N][K]
__global__ void quant_kernel(const float* __restrict__ w0,
                             const float* __restrict__ w1,
                             const float* __restrict__ w2,
                             const float* __restrict__ x) {
    const int t = blockIdx.y;
    const int len = (t == 3) ? KDIM * NDIM : MDIM * KDIM;
    const int i = blockIdx.x * 256 + threadIdx.x;
    if (i >= len) return;
    const float mx = fmaxf(__int_as_float(g_maxbits[t]), 1e-20f);
    const float iq = 127.0f / mx;
    int8_t d1, d2;
    if (t == 3) {
        const int k = i / NDIM, n = i % NDIM;
        quant2(x[i] * iq, d1, d2);
        g_xB1[(size_t)n * KDIM + k] = d1;
        g_xB2[(size_t)n * KDIM + k] = d2;
    } else {
        const float* w = (t == 0) ? w0 : (t == 1) ? w1 : w2;
        int8_t* o1 = (t == 0) ? g_WhxA1 : (t == 1) ? g_WhhA1 : g_WphA1;
        int8_t* o2 = (t == 0) ? g_WhxA2 : (t == 1) ? g_WhhA2 : g_WphA2;
        quant2(w[i] * iq, d1, d2);
        o1[i] = d1;
        o2[i] = d2;
    }
}

// step 1 (h0 = 0): h1 = tanh(c + bh), quantized + transposed to [N][K]
__global__ void first_step_kernel(const float* __restrict__ c,
                                  const float* __restrict__ bh,
                                  int8_t* __restrict__ outB1,
                                  int8_t* __restrict__ outB2) {
    const int i = blockIdx.x * 256 + threadIdx.x;
    if (i >= MDIM * NDIM) return;
    const int n = i >> 11, m = i & 2047;   // i = n*2048 + m
    const float v = tanhf(c[(size_t)m * NDIM + n] + bh[n]);
    int8_t d1, d2;
    quant2(v * 127.0f, d1, d2);
    outB1[i] = d1;
    outB2[i] = d2;
}

// ---------------------------------------------------------------- main GEMM
// D = sA*sB*(A1@B1 + (A1@B2 + A2@B1)/256), A = [M][K] s8x2, B = [N][K] s8x2
// mode 0: outF = D
// mode 1: outF = D + bias
// mode 2: v = tanh(D + addc + bias); quant2(v*127) stored TRANSPOSED [N][K]
__global__ void __launch_bounds__(THREADS) rnn_gemm(
    const int8_t* __restrict__ A1, const int8_t* __restrict__ A2,
    const int8_t* __restrict__ B1, const int8_t* __restrict__ B2,
    const int* __restrict__ maxA, const int* __restrict__ maxB,
    const float* __restrict__ addc, const float* __restrict__ bias,
    float* __restrict__ outF,
    int8_t* __restrict__ outB1, int8_t* __restrict__ outB2,
    int mode)
{
    extern __shared__ __align__(16) char sm[];
    const uint32_t sbase = smem_u32(sm);
    const int tid  = threadIdx.x;
    const int lane = tid & 31;
    const int wid  = tid >> 5;
    const int wm0  = (wid & 1) * 32;     // 2 warps in m
    const int wn0  = (wid >> 1) * 16;    // 4 warps in n
    const int m0   = blockIdx.y * BM;
    const int n0   = blockIdx.x * BN;

    const float sa  = __int_as_float(*maxA) * (1.0f / 127.0f);
    const float sb  = maxB ? __int_as_float(*maxB) * (1.0f / 127.0f)
                           : (1.0f / 127.0f);
    const float sAB = sa * sb;

    int C1[2][2][4] = {};
    int C2[2][2][4] = {};

    // ldmatrix lane offsets (bytes) — same mapping as validated bf16 kernel
    const uint32_t aoff = (uint32_t)((lane & 15) * ROWB + (lane >> 4) * 16);
    const uint32_t boff = (uint32_t)((lane & 7) * ROWB +
                                     ((lane >> 4) & 1) * 8 * ROWB +
                                     ((lane >> 3) & 1) * 16);

    // stage loader: 1024 x 16B chunks, 4 per thread (arr = i, compile-time)
    auto issue_stage = [&](int it) {
        const int s  = it % 3;
        const int k0 = it * BK;
        const uint32_t st = sbase + s * STAGE_BYTES;
        const int row = tid >> 2;
        const int q   = tid & 3;
        #pragma unroll
        for (int i = 0; i < 4; ++i) {
            const int8_t* g;
            if (i == 0)      g = A1 + (size_t)(m0 + row) * KDIM + k0 + q * 16;
            else if (i == 1) g = A2 + (size_t)(m0 + row) * KDIM + k0 + q * 16;
            else if (i == 2) g = B1 + (size_t)(n0 + row) * KDIM + k0 + q * 16;
            else             g = B2 + (size_t)(n0 + row) * KDIM + k0 + q * 16;
            cp16(st + i * ARR_BYTES + row * ROWB + q * 16, g);
        }
        asm volatile("cp.async.commit_group;" ::: "memory");
    };

    issue_stage(0);
    issue_stage(1);

    for (int it = 0; it < NIT; ++it) {
        asm volatile("cp.async.wait_group 1;" ::: "memory");
        __syncthreads();
        if (it + 2 < NIT) issue_stage(it + 2);
        else asm volatile("cp.async.commit_group;" ::: "memory");

        const uint32_t st  = sbase + (it % 3) * STAGE_BYTES;
        const uint32_t sA1 = st;
        const uint32_t sA2 = st + ARR_BYTES;
        const uint32_t sB1 = st + 2 * ARR_BYTES;
        const uint32_t sB2 = st + 3 * ARR_BYTES;

        #pragma unroll
        for (int kk = 0; kk < 2; ++kk) {
            const uint32_t kb = kk * 32;           // 32 int8 = one k32 chunk
            uint32_t a1f[2][4], a2f[2][4], b1f[4], b2f[4];
            ldsm_x4(a1f[0], sA1 + (uint32_t)(wm0 * ROWB) + kb + aoff);
            ldsm_x4(a1f[1], sA1 + (uint32_t)((wm0 + 16) * ROWB) + kb + aoff);
            ldsm_x4(a2f[0], sA2 + (uint32_t)(wm0 * ROWB) + kb + aoff);
            ldsm_x4(a2f[1], sA2 + (uint32_t)((wm0 + 16) * ROWB) + kb + aoff);
            ldsm_x4(b1f, sB1 + (uint32_t)(wn0 * ROWB) + kb + boff);
            ldsm_x4(b2f, sB2 + (uint32_t)(wn0 * ROWB) + kb + boff);
            #pragma unroll
            for (int mt = 0; mt < 2; ++mt)
                #pragma unroll
                for (int nt = 0; nt < 2; ++nt) {
                    mma_s8(C1[mt][nt], a1f[mt], &b1f[nt * 2]);
                    mma_s8(C2[mt][nt], a1f[mt], &b2f[nt * 2]);
                    mma_s8(C2[mt][nt], a2f[mt], &b1f[nt * 2]);
                }
        }
    }

    // ------------------------------------------------------------ epilogue
    if (mode == 2) {
        __syncthreads();    // done reading tile stages; reuse smem
        int8_t* th = (int8_t*)sm;              // [64 n][80] digit-1
        int8_t* tl = (int8_t*)sm + 64 * 80;    // [64 n][80] digit-2
        #pragma unroll
        for (int mt = 0; mt < 2; ++mt)
            #pragma unroll
            for (int nt = 0; nt < 2; ++nt) {
                const int lr = wm0 + mt * 16 + (lane >> 2);
                const int lc = wn0 + nt * 8 + 2 * (lane & 3);
                const int gm = m0 + lr, gn = n0 + lc;
                float2 c0 = *(const float2*)(addc + (size_t)gm * NDIM + gn);
                float2 c1 = *(const float2*)(addc + (size_t)(gm + 8) * NDIM + gn);
                float2 bv = *(const float2*)(bias + gn);
                float d00 = sAB * ((float)C1[mt][nt][0] +
                                   (float)C2[mt][nt][0] * (1.0f / 256.0f));
                float d01 = sAB * ((float)C1[mt][nt][1] +
                                   (float)C2[mt][nt][1] * (1.0f / 256.0f));
                float d10 = sAB * ((float)C1[mt][nt][2] +
                                   (float)C2[mt][nt][2] * (1.0f / 256.0f));
                float d11 = sAB * ((float)C1[mt][nt][3] +
                                   (float)C2[mt][nt][3] * (1.0f / 256.0f));
                float v00 = tanhf(d00 + c0.x + bv.x) * 127.0f;
                float v01 = tanhf(d01 + c0.y + bv.y) * 127.0f;
                float v10 = tanhf(d10 + c1.x + bv.x) * 127.0f;
                float v11 = tanhf(d11 + c1.y + bv.y) * 127.0f;
                int8_t h, l;
                quant2(v00, h, l); th[lc * 80 + lr] = h;       tl[lc * 80 + lr] = l;
                quant2(v01, h, l); th[(lc + 1) * 80 + lr] = h; tl[(lc + 1) * 80 + lr] = l;
                quant2(v10, h, l); th[lc * 80 + lr + 8] = h;   tl[lc * 80 + lr + 8] = l;
                quant2(v11, h, l); th[(lc + 1) * 80 + lr + 8] = h;
                                   tl[(lc + 1) * 80 + lr + 8] = l;
            }
        __syncthreads();
        const int row = tid >> 2;          // n index 0..63
        const int q   = tid & 3;           // 16B chunk
        uint4 vh = *(const uint4*)&th[row * 80 + q * 16];
        uint4 vl = *(const uint4*)&tl[row * 80 + q * 16];
        *(uint4*)&outB1[(size_t)(n0 + row) * KDIM + m0 + q * 16] = vh;
        *(uint4*)&outB2[(size_t)(n0 + row) * KDIM + m0 + q * 16] = vl;
    } else {
        #pragma unroll
        for (int mt = 0; mt < 2; ++mt)
            #pragma unroll
            for (int nt = 0; nt < 2; ++nt) {
                const int lr = wm0 + mt * 16 + (lane >> 2);
                const int lc = wn0 + nt * 8 + 2 * (lane & 3);
                const int gm = m0 + lr, gn = n0 + lc;
                float bx = 0.f, by = 0.f;
                if (mode == 1) {
                    float2 bv = *(const float2*)(bias + gn);
                    bx = bv.x; by = bv.y;
                }
                float2 o0, o1;
                o0.x = sAB * ((float)C1[mt][nt][0] +
                              (float)C2[mt][nt][0] * (1.0f / 256.0f)) + bx;
                o0.y = sAB * ((float)C1[mt][nt][1] +
                              (float)C2[mt][nt][1] * (1.0f / 256.0f)) + by;
                o1.x = sAB * ((float)C1[mt][nt][2] +
                              (float)C2[mt][nt][2] * (1.0f / 256.0f)) + bx;
                o1.y = sAB * ((float)C1[mt][nt][3] +
                              (float)C2[mt][nt][3] * (1.0f / 256.0f)) + by;
                *(float2*)(outF + (size_t)gm * NDIM + gn) = o0;
                *(float2*)(outF + (size_t)(gm + 8) * NDIM + gn) = o1;
            }
    }
}

// ---------------------------------------------------------------- softmax
__global__ __launch_bounds__(256) void softmax_kernel(
    const float* __restrict__ p, float* __restrict__ out)
{
    const int row  = blockIdx.x * 8 + (threadIdx.x >> 5);
    const int lane = threadIdx.x & 31;
    const float* pr = p + (size_t)row * NDIM;
    float v[8];
    float mx = -INFINITY;
    #pragma unroll
    for (int i = 0; i < 8; ++i) { v[i] = pr[lane + 32 * i]; mx = fmaxf(mx, v[i]); }
    #pragma unroll
    for (int o = 16; o > 0; o >>= 1) mx = fmaxf(mx, __shfl_xor_sync(~0u, mx, o));
    float s = 0.f;
    #pragma unroll
    for (int i = 0; i < 8; ++i) { v[i] = expf(v[i] - mx); s += v[i]; }
    #pragma unroll
    for (int o = 16; o > 0; o >>= 1) s += __shfl_xor_sync(~0u, s, o);
    const float inv = 1.0f / s;
    float* orow = out + (size_t)row * NDIM;
    #pragma unroll
    for (int i = 0; i < 8; ++i) orow[lane + 32 * i] = v[i] * inv;
}

// ---------------------------------------------------------------- launch
extern "C" void kernel_launch(void* const* d_in, const int* in_sizes, int n_in,
                              void* d_out, int out_size)
{
    const float* x   = (const float*)d_in[0];
    const float* Whx = (const float*)d_in[1];
    const float* Whh = (const float*)d_in[2];
    const float* Wph = (const float*)d_in[3];
    const float* bh  = (const float*)d_in[4];
    const float* bp  = (const float*)d_in[5];

    int8_t *whx1, *whx2, *whh1, *whh2, *wph1, *wph2;
    int8_t *xb1, *xb2, *h0b1, *h0b2, *h1b1, *h1b2;
    float *c, *p;
    int* maxbits;
    cudaGetSymbolAddress((void**)&whx1, g_WhxA1);
    cudaGetSymbolAddress((void**)&whx2, g_WhxA2);
    cudaGetSymbolAddress((void**)&whh1, g_WhhA1);
    cudaGetSymbolAddress((void**)&whh2, g_WhhA2);
    cudaGetSymbolAddress((void**)&wph1, g_WphA1);
    cudaGetSymbolAddress((void**)&wph2, g_WphA2);
    cudaGetSymbolAddress((void**)&xb1,  g_xB1);
    cudaGetSymbolAddress((void**)&xb2,  g_xB2);
    cudaGetSymbolAddress((void**)&h0b1, g_h0B1);
    cudaGetSymbolAddress((void**)&h0b2, g_h0B2);
    cudaGetSymbolAddress((void**)&h1b1, g_h1B1);
    cudaGetSymbolAddress((void**)&h1b2, g_h1B2);
    cudaGetSymbolAddress((void**)&c,    g_c);
    cudaGetSymbolAddress((void**)&p,    g_p);
    cudaGetSymbolAddress((void**)&maxbits, g_maxbits);

    cudaFuncSetAttribute(rnn_gemm, cudaFuncAttributeMaxDynamicSharedMemorySize,
                         SMEM_BYTES);

    // prep: reset -> maxabs -> quantize (3 launches total)
    reset_kernel<<<1, 32>>>();
    maxabs_kernel<<<dim3(2048, 4), 256>>>(Whx, Whh, Wph, x);
    quant_kernel<<<dim3((MDIM * KDIM + 255) / 256, 4), 256>>>(Whx, Whh, Wph, x);

    const dim3 grid(NDIM / BN, MDIM / BM);   // (4, 32) = 128 CTAs

    // c = Whx @ x
    rnn_gemm<<<grid, THREADS, SMEM_BYTES>>>(whx1, whx2, xb1, xb2,
                                            maxbits + 0, maxbits + 3,
                                            nullptr, nullptr, c,
                                            nullptr, nullptr, 0);

    // step 1: h1 = tanh(c + bh) (h0 = 0)
    first_step_kernel<<<(MDIM * NDIM + 255) / 256, 256>>>(c, bh, h0b1, h0b2);

    // steps 2..256
    int8_t *pb1 = h0b1, *pb2 = h0b2, *nb1 = h1b1, *nb2 = h1b2;
    for (int t = 1; t < NDIM; ++t) {
        rnn_gemm<<<grid, THREADS, SMEM_BYTES>>>(whh1, whh2, pb1, pb2,
                                                maxbits + 1, nullptr,
                                                c, bh, nullptr,
                                                nb1, nb2, 2);
        int8_t* tm;
        tm = pb1; pb1 = nb1; nb1 = tm;
        tm = pb2; pb2 = nb2; nb2 = tm;
    }

    // p = Wph @ h + bp; softmax
    rnn_gemm<<<grid, THREADS, SMEM_BYTES>>>(wph1, wph2, pb1, pb2,
                                            maxbits + 2, nullptr,
                                            nullptr, bp, p,
                                            nullptr, nullptr, 1);
    softmax_kernel<<<MDIM / 8, 256>>>(p, (float*)d_out);
}

// round 7
// speedup vs baseline: 3.8333x; 1.0350x over previous
#include <cuda_runtime.h>
#include <math.h>
#include <stdint.h>

// ---------------------------------------------------------------- dims
constexpr int MDIM = 2048, KDIM = 2048, NDIM = 256;

// ---------------------------------------------------------------- tiling
constexpr int BM = 64, BN = 32, BK = 64;     // BK = 64 int8 per stage row
constexpr int NIT = KDIM / BK;               // 32
constexpr int THREADS = 256;                 // 8 warps: 4 (m) x 2 (n)
constexpr int ROWB = 80;                     // padded row bytes (64 data + 16)
constexpr int ARR_A = 64 * ROWB;             // 5120 B per A digit array
constexpr int ARR_B = 32 * ROWB;             // 2560 B per B digit array
constexpr int OFF_A1 = 0;
constexpr int OFF_A2 = ARR_A;                // 5120
constexpr int OFF_B1 = 2 * ARR_A;            // 10240
constexpr int OFF_B2 = 2 * ARR_A + ARR_B;    // 12800
constexpr int STAGE_BYTES = 2 * ARR_A + 2 * ARR_B;   // 15360
constexpr int SMEM_BYTES = 3 * STAGE_BYTES;          // 46080 (< 48K default)

// ---------------------------------------------------------------- scratch
__device__ int8_t g_WhxA1[MDIM * KDIM];
__device__ int8_t g_WhxA2[MDIM * KDIM];
__device__ int8_t g_WhhA1[MDIM * KDIM];
__device__ int8_t g_WhhA2[MDIM * KDIM];
__device__ int8_t g_WphA1[MDIM * KDIM];
__device__ int8_t g_WphA2[MDIM * KDIM];
__device__ int8_t g_xB1[NDIM * KDIM];
__device__ int8_t g_xB2[NDIM * KDIM];
__device__ int8_t g_h0B1[NDIM * KDIM];
__device__ int8_t g_h0B2[NDIM * KDIM];
__device__ int8_t g_h1B1[NDIM * KDIM];
__device__ int8_t g_h1B2[NDIM * KDIM];
__device__ float  g_c[MDIM * NDIM];
__device__ float  g_p[MDIM * NDIM];
__device__ int    g_maxbits[4];              // maxabs of Whx, Whh, Wph, x

// ---------------------------------------------------------------- helpers
__device__ __forceinline__ uint32_t smem_u32(const void* p) {
    uint32_t a;
    asm("{ .reg .u64 t; cvta.to.shared.u64 t, %1; cvt.u32.u64 %0, t; }"
        : "=r"(a) : "l"(p));
    return a;
}

__device__ __forceinline__ void mma_s8(int* c, const uint32_t* a,
                                       const uint32_t* b) {
    asm volatile(
        "mma.sync.aligned.m16n8k32.row.col.s32.s8.s8.s32 "
        "{%0,%1,%2,%3}, {%4,%5,%6,%7}, {%8,%9}, {%0,%1,%2,%3};"
        : "+r"(c[0]), "+r"(c[1]), "+r"(c[2]), "+r"(c[3])
        : "r"(a[0]), "r"(a[1]), "r"(a[2]), "r"(a[3]), "r"(b[0]), "r"(b[1]));
}

__device__ __forceinline__ void ldsm_x4(uint32_t* r, uint32_t addr) {
    asm volatile("ldmatrix.sync.aligned.m8n8.x4.shared.b16 {%0,%1,%2,%3}, [%4];"
                 : "=r"(r[0]), "=r"(r[1]), "=r"(r[2]), "=r"(r[3]) : "r"(addr));
}

__device__ __forceinline__ void cp16(uint32_t sdst, const void* gsrc) {
    asm volatile("cp.async.cg.shared.global [%0], [%1], 16;"
                 :: "r"(sdst), "l"(gsrc));
}

// quantize q in [-127,127] to two int8 digits: q ~= d1 + d2/256
__device__ __forceinline__ void quant2(float q, int8_t& d1, int8_t& d2) {
    float b1 = rintf(q);
    float b2 = rintf((q - b1) * 256.0f);
    b2 = fminf(fmaxf(b2, -127.0f), 127.0f);
    d1 = (int8_t)(int)b1;
    d2 = (int8_t)(int)b2;
}

// ---------------------------------------------------------------- prep
__global__ void reset_kernel() {
    if (threadIdx.x < 4) g_maxbits[threadIdx.x] = 0;
}

__global__ void maxabs_kernel(const float* __restrict__ w0,
                              const float* __restrict__ w1,
                              const float* __restrict__ w2,
                              const float* __restrict__ x) {
    const int t = blockIdx.y;
    const float* src = (t == 0) ? w0 : (t == 1) ? w1 : (t == 2) ? w2 : x;
    const int len = (t == 3) ? KDIM * NDIM : MDIM * KDIM;
    float m = 0.0f;
    for (int i = blockIdx.x * 256 + threadIdx.x; i < len; i += 2048 * 256)
        m = fmaxf(m, fabsf(src[i]));
    #pragma unroll
    for (int o = 16; o > 0; o >>= 1)
        m = fmaxf(m, __shfl_xor_sync(~0u, m, o));
    if ((threadIdx.x & 31) == 0)
        atomicMax(&g_maxbits[t], __float_as_int(m));
}

__global__ void quant_kernel(const float* __restrict__ w0,
                             const float* __restrict__ w1,
                             const float* __restrict__ w2,
                             const float* __restrict__ x) {
    const int t = blockIdx.y;
    const int len = (t == 3) ? KDIM * NDIM : MDIM * KDIM;
    const int i = blockIdx.x * 256 + threadIdx.x;
    if (i >= len) return;
    const float mx = fmaxf(__int_as_float(g_maxbits[t]), 1e-20f);
    const float iq = 127.0f / mx;
    int8_t d1, d2;
    if (t == 3) {
        const int k = i / NDIM, n = i % NDIM;
        quant2(x[i] * iq, d1, d2);
        g_xB1[(size_t)n * KDIM + k] = d1;
        g_xB2[(size_t)n * KDIM + k] = d2;
    } else {
        const float* w = (t == 0) ? w0 : (t == 1) ? w1 : w2;
        int8_t* o1 = (t == 0) ? g_WhxA1 : (t == 1) ? g_WhhA1 : g_WphA1;
        int8_t* o2 = (t == 0) ? g_WhxA2 : (t == 1) ? g_WhhA2 : g_WphA2;
        quant2(w[i] * iq, d1, d2);
        o1[i] = d1;
        o2[i] = d2;
    }
}

// step 1 (h0 = 0): h1 = tanh(c + bh), quantized + transposed to [N][K]
__global__ void first_step_kernel(const float* __restrict__ c,
                                  const float* __restrict__ bh,
                                  int8_t* __restrict__ outB1,
                                  int8_t* __restrict__ outB2) {
    const int i = blockIdx.x * 256 + threadIdx.x;
    if (i >= MDIM * NDIM) return;
    const int n = i >> 11, m = i & 2047;   // i = n*2048 + m
    const float v = tanhf(c[(size_t)m * NDIM + n] + bh[n]);
    int8_t d1, d2;
    quant2(v * 127.0f, d1, d2);
    outB1[i] = d1;
    outB2[i] = d2;
}

// ---------------------------------------------------------------- main GEMM
// D = sA*sB*(A1@B1 + (A1@B2 + A2@B1)/256), A = [M][K] s8x2, B = [N][K] s8x2
// mode 0: outF = D
// mode 1: outF = D + bias
// mode 2: v = tanh(D + addc + bias); quant2(v*127) stored TRANSPOSED [N][K]
__global__ void __launch_bounds__(THREADS) rnn_gemm(
    const int8_t* __restrict__ A1, const int8_t* __restrict__ A2,
    const int8_t* __restrict__ B1, const int8_t* __restrict__ B2,
    const int* __restrict__ maxA, const int* __restrict__ maxB,
    const float* __restrict__ addc, const float* __restrict__ bias,
    float* __restrict__ outF,
    int8_t* __restrict__ outB1, int8_t* __restrict__ outB2,
    int mode)
{
    extern __shared__ __align__(16) char sm[];
    const uint32_t sbase = smem_u32(sm);
    const int tid  = threadIdx.x;
    const int lane = tid & 31;
    const int wid  = tid >> 5;
    const int wm0  = (wid & 3) * 16;     // 4 warps in m (m16 each)
    const int wn0  = (wid >> 2) * 16;    // 2 warps in n (n16 each)
    const int m0   = blockIdx.y * BM;
    const int n0   = blockIdx.x * BN;

    const float sa  = __int_as_float(*maxA) * (1.0f / 127.0f);
    const float sb  = maxB ? __int_as_float(*maxB) * (1.0f / 127.0f)
                           : (1.0f / 127.0f);
    const float sAB = sa * sb;

    int C1[2][4] = {};
    int C2[2][4] = {};

    // ldmatrix lane offsets (bytes) — same mapping as validated R6 kernel
    const uint32_t aoff = (uint32_t)((lane & 15) * ROWB + (lane >> 4) * 16);
    const uint32_t boff = (uint32_t)((lane & 7) * ROWB +
                                     ((lane >> 4) & 1) * 8 * ROWB +
                                     ((lane >> 3) & 1) * 16);

    // stage loader: 960 x 16B chunks, 3 per thread
    const int arow = tid >> 2;             // 0..63
    const int aq   = tid & 3;              // 0..3
    const int brow = (tid & 127) >> 2;     // 0..31
    auto issue_stage = [&](int it) {
        const int s  = it % 3;
        const int k0 = it * BK;
        const uint32_t st = sbase + s * STAGE_BYTES;
        cp16(st + OFF_A1 + arow * ROWB + aq * 16,
             A1 + (size_t)(m0 + arow) * KDIM + k0 + aq * 16);
        cp16(st + OFF_A2 + arow * ROWB + aq * 16,
             A2 + (size_t)(m0 + arow) * KDIM + k0 + aq * 16);
        const int8_t* gb = ((tid < 128) ? B1 : B2) +
                           (size_t)(n0 + brow) * KDIM + k0 + aq * 16;
        cp16(st + OFF_B1 + (uint32_t)(tid >> 7) * ARR_B + brow * ROWB + aq * 16,
             gb);
        asm volatile("cp.async.commit_group;" ::: "memory");
    };

    issue_stage(0);
    issue_stage(1);

    for (int it = 0; it < NIT; ++it) {
        asm volatile("cp.async.wait_group 1;" ::: "memory");
        __syncthreads();
        if (it + 2 < NIT) issue_stage(it + 2);
        else asm volatile("cp.async.commit_group;" ::: "memory");

        const uint32_t st  = sbase + (it % 3) * STAGE_BYTES;
        const uint32_t sA1 = st + OFF_A1;
        const uint32_t sA2 = st + OFF_A2;
        const uint32_t sB1 = st + OFF_B1;
        const uint32_t sB2 = st + OFF_B2;

        #pragma unroll
        for (int kk = 0; kk < 2; ++kk) {
            const uint32_t kb = kk * 32;           // 32 int8 = one k32 chunk
            uint32_t a1f[4], a2f[4], b1f[4], b2f[4];
            ldsm_x4(a1f, sA1 + (uint32_t)(wm0 * ROWB) + kb + aoff);
            ldsm_x4(a2f, sA2 + (uint32_t)(wm0 * ROWB) + kb + aoff);
            ldsm_x4(b1f, sB1 + (uint32_t)(wn0 * ROWB) + kb + boff);
            ldsm_x4(b2f, sB2 + (uint32_t)(wn0 * ROWB) + kb + boff);
            #pragma unroll
            for (int nt = 0; nt < 2; ++nt) {
                mma_s8(C1[nt], a1f, &b1f[nt * 2]);
                mma_s8(C2[nt], a1f, &b2f[nt * 2]);
                mma_s8(C2[nt], a2f, &b1f[nt * 2]);
            }
        }
    }

    // ------------------------------------------------------------ epilogue
    if (mode == 2) {
        __syncthreads();    // done reading tile stages; reuse smem
        int8_t* th = (int8_t*)sm;              // [32 n][80] digit-1
        int8_t* tl = (int8_t*)sm + 32 * ROWB;  // [32 n][80] digit-2
        #pragma unroll
        for (int nt = 0; nt < 2; ++nt) {
            const int lr = wm0 + (lane >> 2);
            const int lc = wn0 + nt * 8 + 2 * (lane & 3);
            const int gm = m0 + lr, gn = n0 + lc;
            float2 c0 = *(const float2*)(addc + (size_t)gm * NDIM + gn);
            float2 c1 = *(const float2*)(addc + (size_t)(gm + 8) * NDIM + gn);
            float2 bv = *(const float2*)(bias + gn);
            float d00 = sAB * ((float)C1[nt][0] + (float)C2[nt][0] * (1.0f / 256.0f));
            float d01 = sAB * ((float)C1[nt][1] + (float)C2[nt][1] * (1.0f / 256.0f));
            float d10 = sAB * ((float)C1[nt][2] + (float)C2[nt][2] * (1.0f / 256.0f));
            float d11 = sAB * ((float)C1[nt][3] + (float)C2[nt][3] * (1.0f / 256.0f));
            float v00 = tanhf(d00 + c0.x + bv.x) * 127.0f;
            float v01 = tanhf(d01 + c0.y + bv.y) * 127.0f;
            float v10 = tanhf(d10 + c1.x + bv.x) * 127.0f;
            float v11 = tanhf(d11 + c1.y + bv.y) * 127.0f;
            int8_t h, l;
            quant2(v00, h, l); th[lc * ROWB + lr] = h;       tl[lc * ROWB + lr] = l;
            quant2(v01, h, l); th[(lc + 1) * ROWB + lr] = h; tl[(lc + 1) * ROWB + lr] = l;
            quant2(v10, h, l); th[lc * ROWB + lr + 8] = h;   tl[lc * ROWB + lr + 8] = l;
            quant2(v11, h, l); th[(lc + 1) * ROWB + lr + 8] = h;
                               tl[(lc + 1) * ROWB + lr + 8] = l;
        }
        __syncthreads();
        // writeout: 32 rows x 4 chunks x 2 arrays = 256 chunks, 1 per thread
        const int arr = tid >> 7;
        const int rq  = tid & 127;
        const int row = rq >> 2;
        const int q   = rq & 3;
        const int8_t* src = (arr == 0) ? th : tl;
        int8_t* dst = (arr == 0) ? outB1 : outB2;
        uint4 v = *(const uint4*)&src[row * ROWB + q * 16];
        *(uint4*)&dst[(size_t)(n0 + row) * KDIM + m0 + q * 16] = v;
    } else {
        #pragma unroll
        for (int nt = 0; nt < 2; ++nt) {
            const int lr = wm0 + (lane >> 2);
            const int lc = wn0 + nt * 8 + 2 * (lane & 3);
            const int gm = m0 + lr, gn = n0 + lc;
            float bx = 0.f, by = 0.f;
            if (mode == 1) {
                float2 bv = *(const float2*)(bias + gn);
                bx = bv.x; by = bv.y;
            }
            float2 o0, o1;
            o0.x = sAB * ((float)C1[nt][0] + (float)C2[nt][0] * (1.0f / 256.0f)) + bx;
            o0.y = sAB * ((float)C1[nt][1] + (float)C2[nt][1] * (1.0f / 256.0f)) + by;
            o1.x = sAB * ((float)C1[nt][2] + (float)C2[nt][2] * (1.0f / 256.0f)) + bx;
            o1.y = sAB * ((float)C1[nt][3] + (float)C2[nt][3] * (1.0f / 256.0f)) + by;
            *(float2*)(outF + (size_t)gm * NDIM + gn) = o0;
            *(float2*)(outF + (size_t)(gm + 8) * NDIM + gn) = o1;
        }
    }
}

// ---------------------------------------------------------------- softmax
__global__ __launch_bounds__(256) void softmax_kernel(
    const float* __restrict__ p, float* __restrict__ out)
{
    const int row  = blockIdx.x * 8 + (threadIdx.x >> 5);
    const int lane = threadIdx.x & 31;
    const float* pr = p + (size_t)row * NDIM;
    float v[8];
    float mx = -INFINITY;
    #pragma unroll
    for (int i = 0; i < 8; ++i) { v[i] = pr[lane + 32 * i]; mx = fmaxf(mx, v[i]); }
    #pragma unroll
    for (int o = 16; o > 0; o >>= 1) mx = fmaxf(mx, __shfl_xor_sync(~0u, mx, o));
    float s = 0.f;
    #pragma unroll
    for (int i = 0; i < 8; ++i) { v[i] = expf(v[i] - mx); s += v[i]; }
    #pragma unroll
    for (int o = 16; o > 0; o >>= 1) s += __shfl_xor_sync(~0u, s, o);
    const float inv = 1.0f / s;
    float* orow = out + (size_t)row * NDIM;
    #pragma unroll
    for (int i = 0; i < 8; ++i) orow[lane + 32 * i] = v[i] * inv;
}

// ---------------------------------------------------------------- launch
extern "C" void kernel_launch(void* const* d_in, const int* in_sizes, int n_in,
                              void* d_out, int out_size)
{
    const float* x   = (const float*)d_in[0];
    const float* Whx = (const float*)d_in[1];
    const float* Whh = (const float*)d_in[2];
    const float* Wph = (const float*)d_in[3];
    const float* bh  = (const float*)d_in[4];
    const float* bp  = (const float*)d_in[5];

    int8_t *whx1, *whx2, *whh1, *whh2, *wph1, *wph2;
    int8_t *xb1, *xb2, *h0b1, *h0b2, *h1b1, *h1b2;
    float *c, *p;
    int* maxbits;
    cudaGetSymbolAddress((void**)&whx1, g_WhxA1);
    cudaGetSymbolAddress((void**)&whx2, g_WhxA2);
    cudaGetSymbolAddress((void**)&whh1, g_WhhA1);
    cudaGetSymbolAddress((void**)&whh2, g_WhhA2);
    cudaGetSymbolAddress((void**)&wph1, g_WphA1);
    cudaGetSymbolAddress((void**)&wph2, g_WphA2);
    cudaGetSymbolAddress((void**)&xb1,  g_xB1);
    cudaGetSymbolAddress((void**)&xb2,  g_xB2);
    cudaGetSymbolAddress((void**)&h0b1, g_h0B1);
    cudaGetSymbolAddress((void**)&h0b2, g_h0B2);
    cudaGetSymbolAddress((void**)&h1b1, g_h1B1);
    cudaGetSymbolAddress((void**)&h1b2, g_h1B2);
    cudaGetSymbolAddress((void**)&c,    g_c);
    cudaGetSymbolAddress((void**)&p,    g_p);
    cudaGetSymbolAddress((void**)&maxbits, g_maxbits);

    // prep: reset -> maxabs -> quantize (3 launches total)
    reset_kernel<<<1, 32>>>();
    maxabs_kernel<<<dim3(2048, 4), 256>>>(Whx, Whh, Wph, x);
    quant_kernel<<<dim3((MDIM * KDIM + 255) / 256, 4), 256>>>(Whx, Whh, Wph, x);

    const dim3 grid(NDIM / BN, MDIM / BM);   // (8, 32) = 256 CTAs

    // c = Whx @ x
    rnn_gemm<<<grid, THREADS, SMEM_BYTES>>>(whx1, whx2, xb1, xb2,
                                            maxbits + 0, maxbits + 3,
                                            nullptr, nullptr, c,
                                            nullptr, nullptr, 0);

    // step 1: h1 = tanh(c + bh) (h0 = 0)
    first_step_kernel<<<(MDIM * NDIM + 255) / 256, 256>>>(c, bh, h0b1, h0b2);

    // steps 2..256
    int8_t *pb1 = h0b1, *pb2 = h0b2, *nb1 = h1b1, *nb2 = h1b2;
    for (int t = 1; t < NDIM; ++t) {
        rnn_gemm<<<grid, THREADS, SMEM_BYTES>>>(whh1, whh2, pb1, pb2,
                                                maxbits + 1, nullptr,
                                                c, bh, nullptr,
                                                nb1, nb2, 2);
        int8_t* tm;
        tm = pb1; pb1 = nb1; nb1 = tm;
        tm = pb2; pb2 = nb2; nb2 = tm;
    }

    // p = Wph @ h + bp; softmax
    rnn_gemm<<<grid, THREADS, SMEM_BYTES>>>(wph1, wph2, pb1, pb2,
                                            maxbits + 2, nullptr,
                                            nullptr, bp, p,
                                            nullptr, nullptr, 1);
    softmax_kernel<<<MDIM / 8, 256>>>(p, (float*)d_out);
}